// round 14
// baseline (speedup 1.0000x reference)
#include <cuda_runtime.h>
#include <cuda_fp16.h>
#include <math.h>
#include <stdint.h>

#define TT   2048
#define CC   2048
#define HH   16
#define DD   128
#define RR   64
#define WLOC 512
#define CI   512
#define C3   6144

#define SCALE_L 0.08838834764831845f
#define SCALE_G 0.1767766952966369f

// ---------------- scratch (device globals) ----------------
__device__ float g_gatez[4 * TT];
__device__ float g_gate[TT];
__device__ int   g_anygate;
__device__ float g_cos[TT * DD];
__device__ float g_sin[TT * DD];
__device__ float g_ctx[TT * CC];

// fp16 operands. 2-term splits kept only on the (gated, rare) global path.
__device__ __half g_xh[TT * CC];
__device__ __half g_wqh[C3 * CC];
__device__ __half g_woh[CC * CC];
__device__ __half g_i1h[CI * CC];
__device__ __half g_cxh[TT * CC];
__device__ __half g_qkvh[TT * C3], g_qkvl[TT * C3];
__device__ __half g_qrh[HH * TT * RR], g_qrl[HH * TT * RR];
__device__ __half g_krh[HH * TT * RR];
__device__ __half g_vrh[HH * TT * RR];
__device__ __half g_uoh[DD * RR];
__device__ __half g_pkh[RR * DD];
__device__ __half g_pvh[RR * DD];

// ============================================================================
// PTX helpers (plain sm_80+ ISA)
// ============================================================================
__device__ __forceinline__ uint32_t smem_u32(const void* p) {
    uint32_t a;
    asm("{ .reg .u64 t; cvta.to.shared.u64 t, %1; cvt.u32.u64 %0, t; }"
        : "=r"(a) : "l"(p));
    return a;
}

#define CP16(s, g) \
    asm volatile("cp.async.cg.shared.global [%0], [%1], 16;" \
                 :: "r"(s), "l"(g) : "memory")
#define CP_COMMIT() asm volatile("cp.async.commit_group;" ::: "memory")
#define CP_WAIT(n)  asm volatile("cp.async.wait_group %0;" :: "n"(n) : "memory")

__device__ __forceinline__ void ldsm4(uint32_t& r0, uint32_t& r1,
                                      uint32_t& r2, uint32_t& r3, uint32_t a) {
    asm volatile("ldmatrix.sync.aligned.m8n8.x4.shared.b16 {%0,%1,%2,%3}, [%4];"
                 : "=r"(r0), "=r"(r1), "=r"(r2), "=r"(r3) : "r"(a));
}
__device__ __forceinline__ void ldsm4t(uint32_t& r0, uint32_t& r1,
                                       uint32_t& r2, uint32_t& r3, uint32_t a) {
    asm volatile("ldmatrix.sync.aligned.m8n8.x4.trans.shared.b16 {%0,%1,%2,%3}, [%4];"
                 : "=r"(r0), "=r"(r1), "=r"(r2), "=r"(r3) : "r"(a));
}

__device__ __forceinline__ void mma16816(float* c, const uint32_t* a,
                                         const uint32_t* b) {
    asm volatile("mma.sync.aligned.m16n8k16.row.col.f32.f16.f16.f32 "
                 "{%0,%1,%2,%3}, {%4,%5,%6,%7}, {%8,%9}, {%0,%1,%2,%3};"
                 : "+f"(c[0]), "+f"(c[1]), "+f"(c[2]), "+f"(c[3])
                 : "r"(a[0]), "r"(a[1]), "r"(a[2]), "r"(a[3]),
                   "r"(b[0]), "r"(b[1]));
}

__device__ __forceinline__ void split2(float x, float y, uint32_t& h, uint32_t& l) {
    __half2 hh = __floats2half2_rn(x, y);
    h = *reinterpret_cast<uint32_t*>(&hh);
    __half2 ll = __floats2half2_rn(x - __low2float(hh), y - __high2float(hh));
    l = *reinterpret_cast<uint32_t*>(&ll);
}

// ============================================================================
// Fused: fp32 -> fp16 convert of x + ALL weights, AND RoPE tables (one launch)
// ============================================================================
#define CS0 (TT * CC / 2)
#define CS1 (CS0 + C3 * CC / 2)
#define CS2 (CS1 + CI * CC / 2)
#define CS3 (CS2 + CC * CC / 2)
#define CS4 (CS3 + DD * RR / 2)
#define CS5 (CS4 + RR * DD / 2)
#define CS6 (CS5 + RR * DD / 2)
#define CS7 (CS6 + TT * DD)
__global__ void conv_all_k(const float2* __restrict__ x,
                           const float2* __restrict__ wq,
                           const float2* __restrict__ i1,
                           const float2* __restrict__ wo,
                           const float2* __restrict__ uo,
                           const float2* __restrict__ pk,
                           const float2* __restrict__ pv)
{
    int i = blockIdx.x * 256 + threadIdx.x;
    if (i >= CS6) {
        int j = i - CS6;
        if (j < TT * DD) {
            int t = j >> 7, dd = j & 127, e = dd & 63;
            float inv = exp2f(-(float)e * 0.20762050593046014f);
            float ang = (float)t * inv;
            g_cos[j] = cosf(ang);
            g_sin[j] = sinf(ang);
        }
        return;
    }
    const float2* s; __half2* d; int j;
    if      (i < CS0) { s = x;  d = (__half2*)g_xh;  j = i; }
    else if (i < CS1) { s = wq; d = (__half2*)g_wqh; j = i - CS0; }
    else if (i < CS2) { s = i1; d = (__half2*)g_i1h; j = i - CS1; }
    else if (i < CS3) { s = wo; d = (__half2*)g_woh; j = i - CS2; }
    else if (i < CS4) { s = uo; d = (__half2*)g_uoh; j = i - CS3; }
    else if (i < CS5) { s = pk; d = (__half2*)g_pkh; j = i - CS4; }
    else              { s = pv; d = (__half2*)g_pvh; j = i - CS5; }
    float2 v = s[j];
    d[j] = __floats2half2_rn(v.x, v.y);
}

// ============================================================================
// mma.sync GEMM, 1-term fp16: C = Ah·Bh^T.
// BM=128, BN=256, BK=32; 512 threads (warps 4x4, warp tile 32x64).
// mode 0: fp32 store. mode 2: rope + fp16 hi/lo store.
// ============================================================================
__global__ __launch_bounds__(512) void gemm_mma256(
    const __half* __restrict__ Ah, const __half* __restrict__ Bh,
    float* __restrict__ Cout,
    __half* __restrict__ Ch, __half* __restrict__ Cl,
    int N, int K, int mode)
{
    extern __shared__ __align__(128) char smraw[];
    const uint32_t sb = smem_u32(smraw);
    const int tid = threadIdx.x, lane = tid & 31, wid = tid >> 5;
    const int wm = wid & 3, wn = wid >> 2;
    const int bm = blockIdx.y << 7, bn = blockIdx.x << 8;
    const int aj = lane >> 3, ar = lane & 7;

    float acc[2][8][4];
#pragma unroll
    for (int mt = 0; mt < 2; mt++)
#pragma unroll
        for (int nt = 0; nt < 8; nt++)
#pragma unroll
            for (int e = 0; e < 4; e++) acc[mt][nt][e] = 0.f;

    const int nch = K >> 5;

    auto issue_stage = [&](int c) {
        const uint32_t st = sb + (c & 1) * 30720;
        const int k0 = c << 5;
        {
            int r = tid >> 2, q = tid & 3;
            CP16(st + r * 80 + q * 16, Ah + (size_t)(bm + r) * K + k0 + q * 8);
        }
        {
            const __half* gh = Bh + (size_t)bn * K + k0;
#pragma unroll
            for (int hh = 0; hh < 2; hh++) {
                int i = tid + hh * 512;
                int r = i >> 2, q = i & 3;
                CP16(st + 10240 + r * 80 + q * 16, gh + (size_t)r * K + q * 8);
            }
        }
        CP_COMMIT();
    };

    issue_stage(0);
    for (int c = 0; c < nch; c++) {
        if (c + 1 < nch) { issue_stage(c + 1); CP_WAIT(1); }
        else             { CP_WAIT(0); }
        __syncthreads();

        const uint32_t st = sb + (c & 1) * 30720;
#pragma unroll
        for (int ks = 0; ks < 2; ks++) {
            uint32_t ah[2][4], b2[8][2];
            const uint32_t a_off =
                ((wm * 32 + (aj & 1) * 8 + ar) * 40 + ks * 16 + (aj >> 1) * 8) * 2;
            const uint32_t b_off =
                ((wn * 64 + (aj >> 1) * 8 + ar) * 40 + ks * 16 + (aj & 1) * 8) * 2;

#pragma unroll
            for (int mt = 0; mt < 2; mt++)
                ldsm4(ah[mt][0], ah[mt][1], ah[mt][2], ah[mt][3],
                      st + a_off + mt * (16 * 80));
#pragma unroll
            for (int np = 0; np < 4; np++) {
                uint32_t r0, r1, r2, r3;
                ldsm4(r0, r1, r2, r3, st + 10240 + b_off + np * (16 * 80));
                b2[np * 2][0] = r0;     b2[np * 2][1] = r1;
                b2[np * 2 + 1][0] = r2; b2[np * 2 + 1][1] = r3;
            }
#pragma unroll
            for (int mt = 0; mt < 2; mt++)
#pragma unroll
                for (int nt = 0; nt < 8; nt++)
                    mma16816(acc[mt][nt], ah[mt], b2[nt]);
        }
        __syncthreads();
    }

    const int row_base = bm + wm * 32 + (lane >> 2);
    const int col_base = bn + wn * 64 + (lane & 3) * 2;
#pragma unroll
    for (int mt = 0; mt < 2; mt++)
#pragma unroll
        for (int nt = 0; nt < 8; nt++) {
            int r0 = row_base + mt * 16, cc = col_base + nt * 8;
            float v0 = acc[mt][nt][0], v1 = acc[mt][nt][1];
            float v2 = acc[mt][nt][2], v3 = acc[mt][nt][3];
            if (mode == 2) {
                if (cc < 2 * CC) {
                    int d0 = cc & 127;
                    float2 cA = *(const float2*)(g_cos + r0 * DD + d0);
                    float2 sA = *(const float2*)(g_sin + r0 * DD + d0);
                    float o0 = v0 * cA.x - v1 * sA.x;
                    float o1 = v1 * cA.y + v0 * sA.y;
                    float2 cB = *(const float2*)(g_cos + (r0 + 8) * DD + d0);
                    float2 sB = *(const float2*)(g_sin + (r0 + 8) * DD + d0);
                    float o2 = v2 * cB.x - v3 * sB.x;
                    float o3 = v3 * cB.y + v2 * sB.y;
                    v0 = o0; v1 = o1; v2 = o2; v3 = o3;
                }
                uint32_t h01, l01, h23, l23;
                split2(v0, v1, h01, l01);
                split2(v2, v3, h23, l23);
                *(uint32_t*)(Ch + (size_t)r0 * N + cc)       = h01;
                *(uint32_t*)(Cl + (size_t)r0 * N + cc)       = l01;
                *(uint32_t*)(Ch + (size_t)(r0 + 8) * N + cc) = h23;
                *(uint32_t*)(Cl + (size_t)(r0 + 8) * N + cc) = l23;
            } else {
                *(float2*)(Cout + (size_t)r0 * N + cc)       = make_float2(v0, v1);
                *(float2*)(Cout + (size_t)(r0 + 8) * N + cc) = make_float2(v2, v3);
            }
        }
}

// ============================================================================
// Info GEMM: BM=64, BN=128 (grid 4x32 = 128 CTAs for occupancy), 1-term fp16,
// fused gelu + dot(w2) gate partials. 8 warps as 2x4; warp tile 32x32.
// smem/stage: A 5120 | B 10240 = 15360; x2 = 30720.
// ============================================================================
__global__ __launch_bounds__(256) void gemm_info(
    const __half* __restrict__ Ah, const __half* __restrict__ Bh,
    const float* __restrict__ w2, int N, int K)
{
    extern __shared__ __align__(128) char smraw[];
    const uint32_t sb = smem_u32(smraw);
    const int tid = threadIdx.x, lane = tid & 31, wid = tid >> 5;
    const int wm = wid & 1, wn = wid >> 1;       // 2 x 4 warp grid
    const int bm = blockIdx.y << 6, bn = blockIdx.x << 7;
    const int aj = lane >> 3, ar = lane & 7;

    float acc[2][4][4];
#pragma unroll
    for (int mt = 0; mt < 2; mt++)
#pragma unroll
        for (int nt = 0; nt < 4; nt++)
#pragma unroll
            for (int e = 0; e < 4; e++) acc[mt][nt][e] = 0.f;

    const int nch = K >> 5;

    auto issue_stage = [&](int c) {
        const uint32_t st = sb + (c & 1) * 15360;
        const int k0 = c << 5;
#pragma unroll
        for (int hh = 0; hh < 3; hh++) {
            int i = tid + hh * 256;           // 0..767
            if (i < 256) {                    // A: 64 rows x 4 chunks
                int r = i >> 2, q = i & 3;
                CP16(st + r * 80 + q * 16,
                     Ah + (size_t)(bm + r) * K + k0 + q * 8);
            } else {                          // B: 128 rows x 4 chunks
                int j = i - 256;
                int r = j >> 2, q = j & 3;
                CP16(st + 5120 + r * 80 + q * 16,
                     Bh + (size_t)(bn + r) * K + k0 + q * 8);
            }
        }
        CP_COMMIT();
    };

    issue_stage(0);
    for (int c = 0; c < nch; c++) {
        if (c + 1 < nch) { issue_stage(c + 1); CP_WAIT(1); }
        else             { CP_WAIT(0); }
        __syncthreads();

        const uint32_t st = sb + (c & 1) * 15360;
#pragma unroll
        for (int ks = 0; ks < 2; ks++) {
            uint32_t ah[2][4], b2[4][2];
            const uint32_t a_off =
                ((wm * 32 + (aj & 1) * 8 + ar) * 40 + ks * 16 + (aj >> 1) * 8) * 2;
            const uint32_t b_off =
                ((wn * 32 + (aj >> 1) * 8 + ar) * 40 + ks * 16 + (aj & 1) * 8) * 2;

#pragma unroll
            for (int mt = 0; mt < 2; mt++)
                ldsm4(ah[mt][0], ah[mt][1], ah[mt][2], ah[mt][3],
                      st + a_off + mt * (16 * 80));
#pragma unroll
            for (int np = 0; np < 2; np++) {
                uint32_t r0, r1, r2, r3;
                ldsm4(r0, r1, r2, r3, st + 5120 + b_off + np * (16 * 80));
                b2[np * 2][0] = r0;     b2[np * 2][1] = r1;
                b2[np * 2 + 1][0] = r2; b2[np * 2 + 1][1] = r3;
            }
#pragma unroll
            for (int mt = 0; mt < 2; mt++)
#pragma unroll
                for (int nt = 0; nt < 4; nt++)
                    mma16816(acc[mt][nt], ah[mt], b2[nt]);
        }
        __syncthreads();
    }

    // fused gelu + dot(w2): partials per row, reduced across 4 wn groups
    const int col_base = bn + wn * 32 + (lane & 3) * 2;
    float z[2][2] = {{0.f, 0.f}, {0.f, 0.f}};
#pragma unroll
    for (int mt = 0; mt < 2; mt++)
#pragma unroll
        for (int nt = 0; nt < 4; nt++) {
            int cc = col_base + nt * 8;
            float w0 = w2[cc], w1 = w2[cc + 1];
            float v0 = acc[mt][nt][0], v1 = acc[mt][nt][1];
            float v2 = acc[mt][nt][2], v3 = acc[mt][nt][3];
            v0 = 0.5f * v0 * (1.0f + erff(v0 * 0.7071067811865475f));
            v1 = 0.5f * v1 * (1.0f + erff(v1 * 0.7071067811865475f));
            v2 = 0.5f * v2 * (1.0f + erff(v2 * 0.7071067811865475f));
            v3 = 0.5f * v3 * (1.0f + erff(v3 * 0.7071067811865475f));
            z[mt][0] += v0 * w0 + v1 * w1;
            z[mt][1] += v2 * w0 + v3 * w1;
        }
#pragma unroll
    for (int mt = 0; mt < 2; mt++)
#pragma unroll
        for (int e = 0; e < 2; e++) {
            z[mt][e] += __shfl_xor_sync(0xffffffffu, z[mt][e], 1);
            z[mt][e] += __shfl_xor_sync(0xffffffffu, z[mt][e], 2);
        }
    float* zs = (float*)smraw;   // [4][64]
    if ((lane & 3) == 0) {
        int lr = wm * 32 + (lane >> 2);
        zs[wn * 64 + lr +  0] = z[0][0];
        zs[wn * 64 + lr +  8] = z[0][1];
        zs[wn * 64 + lr + 16] = z[1][0];
        zs[wn * 64 + lr + 24] = z[1][1];
    }
    __syncthreads();
    if (tid < 64)
        g_gatez[blockIdx.x * TT + bm + tid] =
            zs[tid] + zs[64 + tid] + zs[128 + tid] + zs[192 + tid];
}

// gate finalize (one block): gates + any-gate flag (sums 4 bn slots)
__global__ __launch_bounds__(512) void gate_fin_k()
{
    int any = 0;
    for (int t = threadIdx.x; t < TT; t += 512) {
        float zsum = g_gatez[t] + g_gatez[TT + t] + g_gatez[2 * TT + t]
                   + g_gatez[3 * TT + t];
        float sc = 1.0f / (1.0f + expf(-zsum));
        float gv = (sc > 0.75f) ? 1.0f : 0.0f;
        g_gate[t] = gv;
        any |= (gv != 0.0f);
    }
    int anyb = __syncthreads_or(any);
    if (threadIdx.x == 0) g_anygate = anyb;
}

// ============================================================================
// Low-rank projections (2-term fp16). Skipped when no gate fires.
// ============================================================================
__global__ __launch_bounds__(128) void lowrank_mma()
{
    if (g_anygate == 0) return;

    extern __shared__ __align__(16) char smraw[];
    const uint32_t sb = smem_u32(smraw);
    const uint32_t oAl = 64 * 136 * 2, oPh = 2 * 64 * 136 * 2;
    const int tid = threadIdx.x, lane = tid & 31, w = tid >> 5;
    const int qt = blockIdx.x, h = blockIdx.y, t0 = qt << 6;
    const int aj = lane >> 3, ar = lane & 7;

    const uint32_t aoff = ((w * 16 + (aj & 1) * 8 + ar) * 136 + (aj >> 1) * 8) * 2;
    const uint32_t boff = (((aj >> 1) * 8 + ar) * 136 + (aj & 1) * 8) * 2;
    const int row0 = t0 + w * 16 + (lane >> 2);
    const int col = (lane & 3) * 2;

    for (int pass = 0; pass < 3; pass++) {
        const __half* Ph = (pass == 2) ? g_pvh : g_pkh;
        const int off = pass * CC + h * DD;
        __syncthreads();
        for (int i = tid; i < 1024; i += 128) {
            int r = i >> 4, q = i & 15;
            uint32_t so = (r * 136 + q * 8) * 2;
            size_t ga = (size_t)(t0 + r) * C3 + off + q * 8;
            CP16(sb + so,       g_qkvh + ga);
            CP16(sb + oAl + so, g_qkvl + ga);
            CP16(sb + oPh + so, Ph + r * DD + q * 8);
        }
        CP_COMMIT(); CP_WAIT(0);
        __syncthreads();

        float acc[8][4];
#pragma unroll
        for (int nt = 0; nt < 8; nt++)
#pragma unroll
            for (int e = 0; e < 4; e++) acc[nt][e] = 0.f;

#pragma unroll
        for (int kb = 0; kb < 8; kb++) {
            uint32_t ah[4], al_[4], b2[8][2];
            ldsm4(ah[0], ah[1], ah[2], ah[3], sb + aoff + kb * 32);
            ldsm4(al_[0], al_[1], al_[2], al_[3], sb + oAl + aoff + kb * 32);
#pragma unroll
            for (int np = 0; np < 4; np++) {
                uint32_t r0, r1, r2, r3;
                ldsm4(r0, r1, r2, r3, sb + oPh + boff + np * 16 * 136 * 2 + kb * 32);
                b2[np * 2][0] = r0;     b2[np * 2][1] = r1;
                b2[np * 2 + 1][0] = r2; b2[np * 2 + 1][1] = r3;
            }
#pragma unroll
            for (int nt = 0; nt < 8; nt++) {
                mma16816(acc[nt], ah, b2[nt]);
                mma16816(acc[nt], al_, b2[nt]);
            }
        }

        if (pass == 0) {
#pragma unroll
            for (int nt = 0; nt < 8; nt++) {
                uint32_t hh, ll;
                size_t i0 = (size_t)(h * TT + row0) * RR + nt * 8 + col;
                split2(acc[nt][0], acc[nt][1], hh, ll);
                *(uint32_t*)(g_qrh + i0) = hh;
                *(uint32_t*)(g_qrl + i0) = ll;
                size_t i1 = i0 + 8 * RR;
                split2(acc[nt][2], acc[nt][3], hh, ll);
                *(uint32_t*)(g_qrh + i1) = hh;
                *(uint32_t*)(g_qrl + i1) = ll;
            }
        } else {
            __half* dh = (pass == 1) ? g_krh : g_vrh;
#pragma unroll
            for (int nt = 0; nt < 8; nt++) {
                size_t i0 = (size_t)(h * TT + row0) * RR + nt * 8 + col;
                __half2 a = __floats2half2_rn(acc[nt][0], acc[nt][1]);
                *(uint32_t*)(dh + i0) = *(uint32_t*)&a;
                size_t i1 = i0 + 8 * RR;
                __half2 b = __floats2half2_rn(acc[nt][2], acc[nt][3]);
                *(uint32_t*)(dh + i1) = *(uint32_t*)&b;
            }
        }
    }
}

// ============================================================================
// Local sliding-window attention: Sq=64, 4 warps, double-buffered KV.
// 1-term QK and 1-term PV. smem = 87040 B -> 2 CTAs/SM.
// ============================================================================
#define LPAD 136
__global__ __launch_bounds__(128) void local_attn_mma()
{
    extern __shared__ __align__(16) char smraw[];
    const uint32_t sb = smem_u32(smraw);
    const uint32_t kvBase = 64 * LPAD * 2;
    const uint32_t kvStage = 2 * 64 * LPAD * 2;
    const uint32_t seg = 64 * LPAD * 2;

    const int tid = threadIdx.x, lane = tid & 31, w = tid >> 5;
    const int qt = gridDim.x - 1 - blockIdx.x, h = blockIdx.y;
    const int t0 = qt << 6;
    const int aj = lane >> 3, ar = lane & 7;
    const int tg0 = t0 + w * 16 + (lane >> 2), tg1 = tg0 + 8;
    const int cq = (lane & 3) * 2;

    for (int i = tid; i < 1024; i += 128) {
        int r = i >> 4, q = i & 15;
        CP16(sb + (r * LPAD + q * 8) * 2,
             g_qkvh + (size_t)(t0 + r) * C3 + h * DD + q * 8);
    }
    CP_COMMIT();

    const int kt0 = (t0 > WLOC - 1) ? ((t0 - (WLOC - 1)) >> 6) : 0;
    const int ktend = qt;

    auto issueKV = [&](int kt, int s) {
        const int s0 = kt << 6;
        const uint32_t kb = sb + kvBase + s * kvStage;
        for (int i = tid; i < 1024; i += 128) {
            int r = i >> 4, q = i & 15;
            size_t gk = (size_t)(s0 + r) * C3 + CC + h * DD + q * 8;
            uint32_t off = (r * LPAD + q * 8) * 2;
            CP16(kb + off,       g_qkvh + gk);
            CP16(kb + seg + off, g_qkvh + gk + CC);
        }
        CP_COMMIT();
    };
    issueKV(kt0, 0);

    float m0 = -1e30f, m1 = -1e30f, l0 = 0.f, l1 = 0.f;
    float out[16][4];
#pragma unroll
    for (int nt = 0; nt < 16; nt++)
#pragma unroll
        for (int e = 0; e < 4; e++) out[nt][e] = 0.f;

    const uint32_t aQoff = ((w * 16 + (aj & 1) * 8 + ar) * LPAD + (aj >> 1) * 8) * 2;
    const uint32_t bKoff = (((aj >> 1) * 8 + ar) * LPAD + (aj & 1) * 8) * 2;
    const uint32_t bVoff = (((aj & 1) * 8 + ar) * LPAD + (aj >> 1) * 8) * 2;

    for (int kt = kt0; kt <= ktend; kt++) {
        const int s = (kt - kt0) & 1;
        if (kt < ktend) { issueKV(kt + 1, s ^ 1); CP_WAIT(1); }
        else            { CP_WAIT(0); }
        __syncthreads();
        const uint32_t kb = sb + kvBase + s * kvStage;
        const int s0 = kt << 6;

        float sc[8][4];
#pragma unroll
        for (int nt = 0; nt < 8; nt++)
#pragma unroll
            for (int e = 0; e < 4; e++) sc[nt][e] = 0.f;

#pragma unroll
        for (int kbk = 0; kbk < 8; kbk++) {
            uint32_t ah[4], b2[8][2];
            ldsm4(ah[0], ah[1], ah[2], ah[3], sb + aQoff + kbk * 32);
#pragma unroll
            for (int np = 0; np < 4; np++) {
                uint32_t r0, r1, r2, r3;
                ldsm4(r0, r1, r2, r3, kb + bKoff + np * 16 * LPAD * 2 + kbk * 32);
                b2[np * 2][0] = r0;     b2[np * 2][1] = r1;
                b2[np * 2 + 1][0] = r2; b2[np * 2 + 1][1] = r3;
            }
#pragma unroll
            for (int nt = 0; nt < 8; nt++)
                mma16816(sc[nt], ah, b2[nt]);
        }

#pragma unroll
        for (int nt = 0; nt < 8; nt++) {
            int c0 = s0 + nt * 8 + cq;
#pragma unroll
            for (int e = 0; e < 2; e++) {
                int sg = c0 + e;
                float v0 = sc[nt][e] * SCALE_L;
                sc[nt][e] = (sg <= tg0 && sg >= tg0 - (WLOC - 1)) ? v0 : -1e30f;
                float v1 = sc[nt][2 + e] * SCALE_L;
                sc[nt][2 + e] = (sg <= tg1 && sg >= tg1 - (WLOC - 1)) ? v1 : -1e30f;
            }
        }

        float mx0 = -1e30f, mx1 = -1e30f;
#pragma unroll
        for (int nt = 0; nt < 8; nt++) {
            mx0 = fmaxf(mx0, fmaxf(sc[nt][0], sc[nt][1]));
            mx1 = fmaxf(mx1, fmaxf(sc[nt][2], sc[nt][3]));
        }
        mx0 = fmaxf(mx0, __shfl_xor_sync(0xffffffffu, mx0, 1));
        mx0 = fmaxf(mx0, __shfl_xor_sync(0xffffffffu, mx0, 2));
        mx1 = fmaxf(mx1, __shfl_xor_sync(0xffffffffu, mx1, 1));
        mx1 = fmaxf(mx1, __shfl_xor_sync(0xffffffffu, mx1, 2));
        float mn0 = fmaxf(m0, mx0), mn1 = fmaxf(m1, mx1);
        float al0 = __expf(m0 - mn0), al1 = __expf(m1 - mn1);
        m0 = mn0; m1 = mn1;

        float sum0 = 0.f, sum1 = 0.f;
#pragma unroll
        for (int nt = 0; nt < 8; nt++) {
#pragma unroll
            for (int e = 0; e < 2; e++) {
                float p0 = (sc[nt][e]     > -1e29f) ? __expf(sc[nt][e]     - mn0) : 0.f;
                float p1 = (sc[nt][2 + e] > -1e29f) ? __expf(sc[nt][2 + e] - mn1) : 0.f;
                sc[nt][e] = p0; sc[nt][2 + e] = p1;
                sum0 += p0; sum1 += p1;
            }
        }
        sum0 += __shfl_xor_sync(0xffffffffu, sum0, 1);
        sum0 += __shfl_xor_sync(0xffffffffu, sum0, 2);
        sum1 += __shfl_xor_sync(0xffffffffu, sum1, 1);
        sum1 += __shfl_xor_sync(0xffffffffu, sum1, 2);
        l0 = l0 * al0 + sum0;
        l1 = l1 * al1 + sum1;

#pragma unroll
        for (int nt = 0; nt < 16; nt++) {
            out[nt][0] *= al0; out[nt][1] *= al0;
            out[nt][2] *= al1; out[nt][3] *= al1;
        }

#pragma unroll
        for (int kbk = 0; kbk < 4; kbk++) {
            uint32_t ph[4];
            __half2 p01 = __floats2half2_rn(sc[2 * kbk][0],     sc[2 * kbk][1]);
            __half2 p23 = __floats2half2_rn(sc[2 * kbk][2],     sc[2 * kbk][3]);
            __half2 p45 = __floats2half2_rn(sc[2 * kbk + 1][0], sc[2 * kbk + 1][1]);
            __half2 p67 = __floats2half2_rn(sc[2 * kbk + 1][2], sc[2 * kbk + 1][3]);
            ph[0] = *(uint32_t*)&p01; ph[1] = *(uint32_t*)&p23;
            ph[2] = *(uint32_t*)&p45; ph[3] = *(uint32_t*)&p67;
#pragma unroll
            for (int g = 0; g < 8; g++) {
                uint32_t r0, r1, r2, r3;
                ldsm4t(r0, r1, r2, r3,
                       kb + seg + bVoff + kbk * 16 * LPAD * 2 + g * 32);
                uint32_t b0[2] = {r0, r1}, b1[2] = {r2, r3};
                mma16816(out[2 * g], ph, b0);
                mma16816(out[2 * g + 1], ph, b1);
            }
        }
        __syncthreads();
    }

    const float inv0 = 1.f / l0, inv1 = 1.f / l1;
#pragma unroll
    for (int nt = 0; nt < 16; nt++) {
        *(float2*)(g_ctx + (size_t)tg0 * CC + h * DD + nt * 8 + cq) =
            make_float2(out[nt][0] * inv0, out[nt][1] * inv0);
        *(float2*)(g_ctx + (size_t)tg1 * CC + h * DD + nt * 8 + cq) =
            make_float2(out[nt][2] * inv1, out[nt][3] * inv1);
    }
}

// ============================================================================
// Global low-rank attention with gated fast path (full 2-term precision on
// the rare gated path).
// ============================================================================
#define GPAD 72
__global__ __launch_bounds__(256) void global_attn_mma()
{
    extern __shared__ __align__(16) char smraw[];
    const uint32_t sb = smem_u32(smraw);
    const uint32_t oQl = 128 * GPAD * 2;
    const uint32_t kvBase = 2 * 128 * GPAD * 2;
    const uint32_t kvStage = 2 * 64 * GPAD * 2;
    const uint32_t seg = 64 * GPAD * 2;
    const uint32_t oUh = kvBase;

    const int tid = threadIdx.x, lane = tid & 31, w = tid >> 5;
    const int qt = blockIdx.x, h = blockIdx.y, t0 = qt << 7;
    const int aj = lane >> 3, ar = lane & 7;
    const int tg0 = t0 + w * 16 + (lane >> 2), tg1 = tg0 + 8;
    const int cq = (lane & 3) * 2;

    int any = 0;
    for (int i = tid; i < 128; i += 256) any |= (g_gate[t0 + i] != 0.0f);
    if (!__syncthreads_or(any)) {
        for (int i = tid; i < 8192; i += 256) {
            int r = i >> 6, c2 = (i & 63) * 2;
            size_t idx = (size_t)(t0 + r) * CC + h * DD + c2;
            float2 v = *(const float2*)(g_ctx + idx);
            __half2 hv = __floats2half2_rn(v.x, v.y);
            *(uint32_t*)(g_cxh + idx) = *(uint32_t*)&hv;
        }
        return;
    }

    for (int i = tid; i < 1024; i += 256) {
        int r = i >> 3, q = i & 7;
        uint32_t so = sb + (r * GPAD + q * 8) * 2;
        size_t go = (size_t)(h * TT + t0 + r) * RR + q * 8;
        CP16(so, g_qrh + go);
        CP16(so + oQl, g_qrl + go);
    }
    CP_COMMIT();

    auto issueKV = [&](int kt, int s) {
        const int s0 = kt << 6;
        const uint32_t kb = sb + kvBase + s * kvStage;
        for (int i = tid; i < 512; i += 256) {
            int r = i >> 3, q = i & 7;
            size_t gk = (size_t)(h * TT + s0 + r) * RR + q * 8;
            uint32_t off = (r * GPAD + q * 8) * 2;
            CP16(kb + off,       g_krh + gk);
            CP16(kb + seg + off, g_vrh + gk);
        }
        CP_COMMIT();
    };
    issueKV(0, 0);

    float m0 = -1e30f, m1 = -1e30f, l0 = 0.f, l1 = 0.f;
    float out[8][4];
#pragma unroll
    for (int nt = 0; nt < 8; nt++)
#pragma unroll
        for (int e = 0; e < 4; e++) out[nt][e] = 0.f;

    const uint32_t aQoff = ((w * 16 + (aj & 1) * 8 + ar) * GPAD + (aj >> 1) * 8) * 2;
    const uint32_t bKoff = (((aj >> 1) * 8 + ar) * GPAD + (aj & 1) * 8) * 2;
    const uint32_t bVoff = (((aj & 1) * 8 + ar) * GPAD + (aj >> 1) * 8) * 2;

    for (int kt = 0; kt < TT / 64; kt++) {
        const int s = kt & 1;
        if (kt < TT / 64 - 1) { issueKV(kt + 1, s ^ 1); CP_WAIT(1); }
        else                  { CP_WAIT(0); }
        __syncthreads();
        const uint32_t kb = sb + kvBase + s * kvStage;

        float sc[8][4];
#pragma unroll
        for (int nt = 0; nt < 8; nt++)
#pragma unroll
            for (int e = 0; e < 4; e++) sc[nt][e] = 0.f;

#pragma unroll
        for (int kbk = 0; kbk < 4; kbk++) {
            uint32_t ah[4], al_[4], b2[8][2];
            ldsm4(ah[0], ah[1], ah[2], ah[3], sb + aQoff + kbk * 32);
            ldsm4(al_[0], al_[1], al_[2], al_[3], sb + oQl + aQoff + kbk * 32);
#pragma unroll
            for (int np = 0; np < 4; np++) {
                uint32_t r0, r1, r2, r3;
                ldsm4(r0, r1, r2, r3, kb + bKoff + np * 16 * GPAD * 2 + kbk * 32);
                b2[np * 2][0] = r0;     b2[np * 2][1] = r1;
                b2[np * 2 + 1][0] = r2; b2[np * 2 + 1][1] = r3;
            }
#pragma unroll
            for (int nt = 0; nt < 8; nt++) {
                mma16816(sc[nt], ah, b2[nt]);
                mma16816(sc[nt], al_, b2[nt]);
            }
        }

        float mx0 = -1e30f, mx1 = -1e30f;
#pragma unroll
        for (int nt = 0; nt < 8; nt++) {
            sc[nt][0] *= SCALE_G; sc[nt][1] *= SCALE_G;
            sc[nt][2] *= SCALE_G; sc[nt][3] *= SCALE_G;
            mx0 = fmaxf(mx0, fmaxf(sc[nt][0], sc[nt][1]));
            mx1 = fmaxf(mx1, fmaxf(sc[nt][2], sc[nt][3]));
        }
        mx0 = fmaxf(mx0, __shfl_xor_sync(0xffffffffu, mx0, 1));
        mx0 = fmaxf(mx0, __shfl_xor_sync(0xffffffffu, mx0, 2));
        mx1 = fmaxf(mx1, __shfl_xor_sync(0xffffffffu, mx1, 1));
        mx1 = fmaxf(mx1, __shfl_xor_sync(0xffffffffu, mx1, 2));
        float mn0 = fmaxf(m0, mx0), mn1 = fmaxf(m1, mx1);
        float al0 = __expf(m0 - mn0), al1 = __expf(m1 - mn1);
        m0 = mn0; m1 = mn1;

        float sum0 = 0.f, sum1 = 0.f;
#pragma unroll
        for (int nt = 0; nt < 8; nt++) {
#pragma unroll
            for (int e = 0; e < 2; e++) {
                float p0 = __expf(sc[nt][e] - mn0);
                float p1 = __expf(sc[nt][2 + e] - mn1);
                sc[nt][e] = p0; sc[nt][2 + e] = p1;
                sum0 += p0; sum1 += p1;
            }
        }
        sum0 += __shfl_xor_sync(0xffffffffu, sum0, 1);
        sum0 += __shfl_xor_sync(0xffffffffu, sum0, 2);
        sum1 += __shfl_xor_sync(0xffffffffu, sum1, 1);
        sum1 += __shfl_xor_sync(0xffffffffu, sum1, 2);
        l0 = l0 * al0 + sum0;
        l1 = l1 * al1 + sum1;

#pragma unroll
        for (int nt = 0; nt < 8; nt++) {
            out[nt][0] *= al0; out[nt][1] *= al0;
            out[nt][2] *= al1; out[nt][3] *= al1;
        }

#pragma unroll
        for (int kbk = 0; kbk < 4; kbk++) {
            uint32_t ph[4], pl[4];
            split2(sc[2 * kbk][0],     sc[2 * kbk][1],     ph[0], pl[0]);
            split2(sc[2 * kbk][2],     sc[2 * kbk][3],     ph[1], pl[1]);
            split2(sc[2 * kbk + 1][0], sc[2 * kbk + 1][1], ph[2], pl[2]);
            split2(sc[2 * kbk + 1][2], sc[2 * kbk + 1][3], ph[3], pl[3]);
#pragma unroll
            for (int g = 0; g < 4; g++) {
                uint32_t r0, r1, r2, r3;
                ldsm4t(r0, r1, r2, r3,
                       kb + seg + bVoff + kbk * 16 * GPAD * 2 + g * 32);
                uint32_t b0[2] = {r0, r1}, b1[2] = {r2, r3};
                mma16816(out[2 * g], ph, b0);     mma16816(out[2 * g + 1], ph, b1);
                mma16816(out[2 * g], pl, b0);     mma16816(out[2 * g + 1], pl, b1);
            }
        }
        __syncthreads();
    }

    const float inv0 = 1.f / l0, inv1 = 1.f / l1;
#pragma unroll
    for (int nt = 0; nt < 8; nt++) {
        out[nt][0] *= inv0; out[nt][1] *= inv0;
        out[nt][2] *= inv1; out[nt][3] *= inv1;
    }

    for (int i = tid; i < 1024; i += 256) {
        int d = i >> 3, q = i & 7;
        *(int4*)(smraw + oUh + (d * GPAD + q * 8) * 2) =
            *(const int4*)(g_uoh + d * 64 + q * 8);
    }
    __syncthreads();

    float out2[16][4];
#pragma unroll
    for (int nt = 0; nt < 16; nt++)
#pragma unroll
        for (int e = 0; e < 4; e++) out2[nt][e] = 0.f;

    const uint32_t bUoff = (((aj >> 1) * 8 + ar) * GPAD + (aj & 1) * 8) * 2;
#pragma unroll
    for (int kbk = 0; kbk < 4; kbk++) {
        uint32_t ph[4], pl[4];
        split2(out[2 * kbk][0],     out[2 * kbk][1],     ph[0], pl[0]);
        split2(out[2 * kbk][2],     out[2 * kbk][3],     ph[1], pl[1]);
        split2(out[2 * kbk + 1][0], out[2 * kbk + 1][1], ph[2], pl[2]);
        split2(out[2 * kbk + 1][2], out[2 * kbk + 1][3], ph[3], pl[3]);
#pragma unroll
        for (int g = 0; g < 8; g++) {
            uint32_t r0, r1, r2, r3;
            ldsm4(r0, r1, r2, r3, sb + oUh + bUoff + g * 16 * GPAD * 2 + kbk * 32);
            uint32_t b0[2] = {r0, r1}, b1[2] = {r2, r3};
            mma16816(out2[2 * g], ph, b0);     mma16816(out2[2 * g + 1], ph, b1);
            mma16816(out2[2 * g], pl, b0);     mma16816(out2[2 * g + 1], pl, b1);
        }
    }

    const float ga0 = g_gate[tg0], ga1 = g_gate[tg1];
#pragma unroll
    for (int nt = 0; nt < 16; nt++) {
        size_t i0 = (size_t)tg0 * CC + h * DD + nt * 8 + cq;
        float2 o0 = *(float2*)(g_ctx + i0);
        __half2 h0 = __floats2half2_rn(o0.x + ga0 * out2[nt][0],
                                       o0.y + ga0 * out2[nt][1]);
        *(uint32_t*)(g_cxh + i0) = *(uint32_t*)&h0;
        size_t i1 = (size_t)tg1 * CC + h * DD + nt * 8 + cq;
        float2 o1 = *(float2*)(g_ctx + i1);
        __half2 h1 = __floats2half2_rn(o1.x + ga1 * out2[nt][2],
                                       o1.y + ga1 * out2[nt][3]);
        *(uint32_t*)(g_cxh + i1) = *(uint32_t*)&h1;
    }
}

// ============================================================================
extern "C" void kernel_launch(void* const* d_in, const int* in_sizes, int n_in,
                              void* d_out, int out_size)
{
    const float* x     = (const float*)d_in[0];
    const float* w_qkv = (const float*)d_in[1];
    const float* w_o   = (const float*)d_in[2];
    const float* pk    = (const float*)d_in[3];
    const float* pv    = (const float*)d_in[4];
    const float* uo    = (const float*)d_in[5];
    const float* iw1   = (const float*)d_in[6];
    const float* iw2   = (const float*)d_in[7];
    float* out = (float*)d_out;

    cudaFuncSetAttribute(gemm_mma256,     cudaFuncAttributeMaxDynamicSharedMemorySize, 61440);
    cudaFuncSetAttribute(gemm_info,       cudaFuncAttributeMaxDynamicSharedMemorySize, 30720);
    cudaFuncSetAttribute(local_attn_mma,  cudaFuncAttributeMaxDynamicSharedMemorySize, 87040);
    cudaFuncSetAttribute(global_attn_mma, cudaFuncAttributeMaxDynamicSharedMemorySize, 73728);
    cudaFuncSetAttribute(lowrank_mma,     cudaFuncAttributeMaxDynamicSharedMemorySize, 52224);

    void *pxh, *pwqh, *pwoh, *pi1h, *pcxh, *pqkvh, *pqkvl;
    cudaGetSymbolAddress(&pxh, g_xh);
    cudaGetSymbolAddress(&pwqh, g_wqh);
    cudaGetSymbolAddress(&pwoh, g_woh);
    cudaGetSymbolAddress(&pi1h, g_i1h);
    cudaGetSymbolAddress(&pcxh, g_cxh);
    cudaGetSymbolAddress(&pqkvh, g_qkvh); cudaGetSymbolAddress(&pqkvl, g_qkvl);

    // fused convert + rope tables (one launch)
    conv_all_k<<<(CS7 + 255) / 256, 256>>>(
        (const float2*)x, (const float2*)w_qkv, (const float2*)iw1,
        (const float2*)w_o, (const float2*)uo, (const float2*)pk,
        (const float2*)pv);

    // qkv = rope(x @ w_qkv^T) -> fp16 splits (1-term GEMM)
    gemm_mma256<<<dim3(C3 / 256, TT / 128), 512, 61440>>>(
        (const __half*)pxh, (const __half*)pwqh,
        nullptr, (__half*)pqkvh, (__half*)pqkvl, C3, CC, 2);

    // info gate: BM=64 GEMM (128 CTAs) + fused gelu/dot partials; finalize
    gemm_info<<<dim3(CI / 128, TT / 64), 256, 30720>>>(
        (const __half*)pxh, (const __half*)pi1h, iw2, CI, CC);
    gate_fin_k<<<1, 512>>>();

    lowrank_mma<<<dim3(TT / 64, HH), 128, 52224>>>();
    local_attn_mma<<<dim3(TT / 64, HH), 128, 87040>>>();
    global_attn_mma<<<dim3(TT / 128, HH), 256, 73728>>>();

    // out = ctx @ w_o^T (1-term GEMM)
    gemm_mma256<<<dim3(CC / 256, TT / 128), 512, 61440>>>(
        (const __half*)pcxh, (const __half*)pwoh,
        out, nullptr, nullptr, CC, CC, 0);
}